// round 13
// baseline (speedup 1.0000x reference)
#include <cuda_runtime.h>
#include <cuda_fp16.h>
#include <cstdint>

#define Bn   4
#define Sn   4096
#define Dn   1024
#define Hn   16
#define HKVn 4
#define DHn  64
#define Mtok (Bn*Sn)            // 16384

// Q pre-scale: (1/sqrt(64)) * log2(e) so attention can use ex2 directly
#define QSCALE 0.18033688011112042f

// ---- scratch ----
__device__ __half g_xh [Mtok * Dn];
__device__ __half g_qh [Bn * Hn   * Sn * DHn];
__device__ __half g_kh [Bn * HKVn * Sn * DHn];
__device__ __half g_vh [Bn * HKVn * Sn * DHn];
__device__ __half g_ah [Mtok * Hn * DHn];
__device__ __half g_wqkv[1536 * Dn];
__device__ __half g_wo  [Hn * DHn * Dn];

// ============================================================
// helpers
// ============================================================
__device__ __forceinline__ uint32_t smem_u32(const void* p) {
    uint32_t a;
    asm("{ .reg .u64 t; cvta.to.shared.u64 t, %1; cvt.u32.u64 %0, t; }" : "=r"(a) : "l"(p));
    return a;
}
__device__ __forceinline__ void cp16(uint32_t dst, const void* src) {
    asm volatile("cp.async.cg.shared.global [%0], [%1], 16;" :: "r"(dst), "l"(src));
}
#define CP_COMMIT() asm volatile("cp.async.commit_group;" ::: "memory")
#define CP_WAIT0()  asm volatile("cp.async.wait_group 0;" ::: "memory")
#define CP_WAIT1()  asm volatile("cp.async.wait_group 1;" ::: "memory")
#define CP_WAIT2()  asm volatile("cp.async.wait_group 2;" ::: "memory")

__device__ __forceinline__ void ldmx4(uint32_t* r, uint32_t addr) {
    asm volatile("ldmatrix.sync.aligned.m8n8.x4.shared.b16 {%0,%1,%2,%3}, [%4];"
        : "=r"(r[0]), "=r"(r[1]), "=r"(r[2]), "=r"(r[3]) : "r"(addr));
}
__device__ __forceinline__ void ldmx4t(uint32_t* r, uint32_t addr) {
    asm volatile("ldmatrix.sync.aligned.m8n8.x4.trans.shared.b16 {%0,%1,%2,%3}, [%4];"
        : "=r"(r[0]), "=r"(r[1]), "=r"(r[2]), "=r"(r[3]) : "r"(addr));
}
__device__ __forceinline__ void mma16816(float* c, const uint32_t* a, const uint32_t* b) {
    asm volatile("mma.sync.aligned.m16n8k16.row.col.f32.f16.f16.f32 "
        "{%0,%1,%2,%3}, {%4,%5,%6,%7}, {%8,%9}, {%0,%1,%2,%3};"
        : "+f"(c[0]), "+f"(c[1]), "+f"(c[2]), "+f"(c[3])
        : "r"(a[0]), "r"(a[1]), "r"(a[2]), "r"(a[3]), "r"(b[0]), "r"(b[1]));
}
__device__ __forceinline__ uint32_t pack_h2(float a, float b) {
    __half2 h = __floats2half2_rn(a, b);
    return *reinterpret_cast<uint32_t*>(&h);
}
__device__ __forceinline__ float ex2f(float x) {
    float y;
    asm("ex2.approx.ftz.f32 %0, %1;" : "=f"(y) : "f"(x));
    return y;
}

// ============================================================
// merged prep kernel: x fp32->fp16 (MLP=4) + 4 weight transposes
// ============================================================
__global__ __launch_bounds__(256) void prep_kernel(
    const float* __restrict__ x,
    const float* __restrict__ Wq, const float* __restrict__ Wk,
    const float* __restrict__ Wv, const float* __restrict__ Wo,
    __half* __restrict__ xh, __half* __restrict__ wqkv, __half* __restrict__ wo)
{
    const int bid = blockIdx.x;
    const int t = threadIdx.x;

    if (bid >= 2560) {
        int base = (bid - 2560) * 1024 + t;
        float4 v[4];
#pragma unroll
        for (int u = 0; u < 4; u++) v[u] = ((const float4*)x)[base + u * 256];
#pragma unroll
        for (int u = 0; u < 4; u++) {
            ushort4 o;
            o.x = __half_as_ushort(__float2half_rn(v[u].x));
            o.y = __half_as_ushort(__float2half_rn(v[u].y));
            o.z = __half_as_ushort(__float2half_rn(v[u].z));
            o.w = __half_as_ushort(__float2half_rn(v[u].w));
            ((ushort4*)xh)[base + u * 256] = o;
        }
        return;
    }

    __shared__ float tile[32][33];
    const float* W;
    __half* dst;
    int N, base;
    if (bid < 1024)      { W = Wq; dst = wqkv;               N = 1024; base = bid; }
    else if (bid < 1280) { W = Wk; dst = wqkv + 1024 * 1024; N = 256;  base = bid - 1024; }
    else if (bid < 1536) { W = Wv; dst = wqkv + 1280 * 1024; N = 256;  base = bid - 1280; }
    else                 { W = Wo; dst = wo;                 N = 1024; base = bid - 1536; }

    const int nblk = N >> 5;
    const int n0 = (base % nblk) * 32;
    const int k0 = (base / nblk) * 32;
    const int tx = t & 31, ty = t >> 5;

    for (int r = ty; r < 32; r += 8)
        tile[r][tx] = W[(size_t)(k0 + r) * N + n0 + tx];
    __syncthreads();
    for (int r = ty; r < 32; r += 8)
        dst[(size_t)(n0 + r) * 1024 + k0 + tx] = __float2half_rn(tile[tx][r]);
}

// ============================================================
// GEMM mainloop: 64x128 CTA tile, 4 warps, 32x64 warp tile.
// BK=32, 4-stage (12KB each) cp.async ring, 2 chunks per sync window.
// 3 CTAs/SM -> 444 concurrent CTAs (wave-quantization smoothing).
// Stage layout: A (64x32 half, 4KB) at +0, B (128x32 half, 8KB) at +4096.
// ============================================================
#define STAGE_LOAD_CH(buf, c) do { \
    uint32_t sb_ = sbase + (uint32_t)(buf) * 12288u; \
    _Pragma("unroll") \
    for (int i_ = 0; i_ < 2; i_++) { \
        int idx_ = t + i_ * 128; \
        int row_ = idx_ >> 2; \
        int lc_  = idx_ & 3; \
        uint32_t sw_ = (uint32_t)row_ * 64u + (uint32_t)((lc_ ^ ((row_ >> 1) & 3)) << 4); \
        cp16(sb_ + sw_, gA + (size_t)row_ * (size_t)Kd + (size_t)(c) * 32 + lc_ * 8); \
    } \
    _Pragma("unroll") \
    for (int i_ = 0; i_ < 4; i_++) { \
        int idx_ = t + i_ * 128; \
        int row_ = idx_ >> 2; \
        int lc_  = idx_ & 3; \
        uint32_t sw_ = (uint32_t)row_ * 64u + (uint32_t)((lc_ ^ ((row_ >> 1) & 3)) << 4); \
        cp16(sb_ + 4096u + sw_, gB + (size_t)row_ * (size_t)Kd + (size_t)(c) * 32 + lc_ * 8); \
    } } while (0)

#define GEMM_COMPUTE_CH(cc) do { \
    const uint32_t sb = sbase + (uint32_t)((cc) & 3) * 12288u; \
    _Pragma("unroll") \
    for (int ks = 0; ks < 2; ks++) { \
        uint32_t ahf[2][4], bhf[4][4]; \
        _Pragma("unroll") \
        for (int mt = 0; mt < 2; mt++) { \
            int r = a_row + mt * 16; \
            uint32_t ad = sb + (uint32_t)r * 64u + \
                          (uint32_t)(((ks * 2 + a_k8) ^ ((r >> 1) & 3)) << 4); \
            ldmx4(ahf[mt], ad); \
        } \
        _Pragma("unroll") \
        for (int g = 0; g < 4; g++) { \
            int r = b_row + g * 16; \
            uint32_t bd = sb + 4096u + (uint32_t)r * 64u + \
                          (uint32_t)(((ks * 2 + b_k8) ^ ((r >> 1) & 3)) << 4); \
            ldmx4(bhf[g], bd); \
        } \
        _Pragma("unroll") \
        for (int mt = 0; mt < 2; mt++) \
            _Pragma("unroll") \
            for (int j = 0; j < 8; j++) \
                mma16816(acc[mt][j], ahf[mt], &bhf[j >> 1][(j & 1) * 2]); \
    } } while (0)

#define GEMM_MAINLOOP(Agl, Bgl, Kdim) do { \
    const __half* gA = (Agl); \
    const __half* gB = (Bgl); \
    const int Kd = (Kdim); \
    const int NCH = Kd >> 5; \
    _Pragma("unroll") \
    for (int s = 0; s < 4; s++) { STAGE_LOAD_CH(s, s); CP_COMMIT(); } \
    for (int c = 0; c < NCH; c += 2) { \
        CP_WAIT2(); \
        __syncthreads(); \
        GEMM_COMPUTE_CH(c); \
        GEMM_COMPUTE_CH(c + 1); \
        __syncthreads(); \
        if (c + 4 < NCH) STAGE_LOAD_CH(c & 3, c + 4); \
        CP_COMMIT(); \
        if (c + 5 < NCH) STAGE_LOAD_CH((c + 1) & 3, c + 5); \
        CP_COMMIT(); \
    } } while (0)

// ============================================================
// Fused QKV GEMM + bias + RMSNorm + RoPE + fp16 transpose store.
// CTA tile 64x128; warp_m = wid&1 (32 rows), warp_n = wid>>1 (64 cols = head).
// ============================================================
__global__ __launch_bounds__(128, 3) void mm_qkv_fused_kernel(
    const __half* __restrict__ Ah, const __half* __restrict__ Bw,
    const float* __restrict__ bq, const float* __restrict__ bk,
    const float* __restrict__ bv,
    const float* __restrict__ qnw, const float* __restrict__ knw,
    const float* __restrict__ cosT, const float* __restrict__ sinT,
    __half* __restrict__ qh, __half* __restrict__ kh, __half* __restrict__ vh)
{
    extern __shared__ char sm[];
    const int t = threadIdx.x, wid = t >> 5, lane = t & 31;
    const int m0 = blockIdx.y * 64, n0 = blockIdx.x * 128;
    const uint32_t sbase = smem_u32(sm);

    const int warp_m = wid & 1;
    const int warp_n = wid >> 1;
    const int a_row = warp_m * 32 + (lane & 15);
    const int a_k8  = lane >> 4;
    const int b_row = warp_n * 64 + (lane & 7) + ((lane >> 4) << 3);
    const int b_k8  = (lane >> 3) & 1;

    float acc[2][8][4];
#pragma unroll
    for (int a = 0; a < 2; a++)
#pragma unroll
        for (int b = 0; b < 8; b++)
#pragma unroll
            for (int cq = 0; cq < 4; cq++) acc[a][b][cq] = 0.0f;

    GEMM_MAINLOOP(Ah + (size_t)m0 * Dn, Bw + (size_t)n0 * Dn, Dn);

    const int gc = n0 + warp_n * 64;
    const int q2 = (lane & 3) * 2;

    int mode, hh, NHd;
    __half* dst;
    const float* bptr;
    const float* wn = qnw;
    if (gc < 1024)      { mode = 0; hh = gc >> 6;          dst = qh; bptr = bq + gc;          wn = qnw; NHd = Hn;  }
    else if (gc < 1280) { mode = 1; hh = (gc - 1024) >> 6; dst = kh; bptr = bk + (gc - 1024); wn = knw; NHd = HKVn; }
    else                { mode = 2; hh = (gc - 1280) >> 6; dst = vh; bptr = bv + (gc - 1280); NHd = HKVn; }

    float bvv[8][2], wnv[8][2];
#pragma unroll
    for (int j = 0; j < 8; j++) {
        bvv[j][0] = bptr[j * 8 + q2];
        bvv[j][1] = bptr[j * 8 + q2 + 1];
    }
    if (mode < 2) {
#pragma unroll
        for (int j = 0; j < 8; j++) {
            wnv[j][0] = wn[j * 8 + q2];
            wnv[j][1] = wn[j * 8 + q2 + 1];
        }
    }

#pragma unroll
    for (int mt = 0; mt < 2; mt++) {
#pragma unroll
        for (int pr = 0; pr < 2; pr++) {
            const int row = m0 + warp_m * 32 + (lane >> 2) + mt * 16 + pr * 8;
            const int s  = row & (Sn - 1);
            const int bb = row >> 12;
            float v[8][2];
#pragma unroll
            for (int j = 0; j < 8; j++) {
                v[j][0] = acc[mt][j][pr * 2]     + bvv[j][0];
                v[j][1] = acc[mt][j][pr * 2 + 1] + bvv[j][1];
            }
            if (mode < 2) {
                float ss = 0.0f;
#pragma unroll
                for (int j = 0; j < 8; j++) ss += v[j][0] * v[j][0] + v[j][1] * v[j][1];
                ss += __shfl_xor_sync(0xffffffffu, ss, 1);
                ss += __shfl_xor_sync(0xffffffffu, ss, 2);
                float r = rsqrtf(ss * (1.0f / 64.0f) + 1e-6f);
#pragma unroll
                for (int j = 0; j < 8; j++) {
                    v[j][0] *= r * wnv[j][0];
                    v[j][1] *= r * wnv[j][1];
                }
                const float* cr = cosT + s * 64;
                const float* sr = sinT + s * 64;
#pragma unroll
                for (int j = 0; j < 4; j++) {
#pragma unroll
                    for (int p = 0; p < 2; p++) {
                        int d = j * 8 + q2 + p;
                        float x0 = v[j][p], x1 = v[j + 4][p];
                        v[j][p]     = x0 * cr[d]      - x1 * sr[d];
                        v[j + 4][p] = x1 * cr[d + 32] + x0 * sr[d + 32];
                    }
                }
                if (mode == 0) {
#pragma unroll
                    for (int j = 0; j < 8; j++) { v[j][0] *= QSCALE; v[j][1] *= QSCALE; }
                }
            }
            __half* dp = dst + (((size_t)(bb * NHd + hh)) * Sn + s) * 64;
#pragma unroll
            for (int j = 0; j < 8; j++)
                *(uint32_t*)(dp + j * 8 + q2) = pack_h2(v[j][0], v[j][1]);
        }
    }
}

// ============================================================
// Standard HMMA GEMM (O-projection): f32 acc, 64x128 CTA tile.
// ============================================================
__global__ __launch_bounds__(128, 3) void mm_hmma_kernel(
    const __half* __restrict__ Ah, const __half* __restrict__ Bh,
    const float* __restrict__ bias, float* __restrict__ Cm, int N, int K)
{
    extern __shared__ char sm[];
    const int t = threadIdx.x, wid = t >> 5, lane = t & 31;
    const int m0 = blockIdx.y * 64, n0 = blockIdx.x * 128;
    const uint32_t sbase = smem_u32(sm);

    const int warp_m = wid & 1;
    const int warp_n = wid >> 1;
    const int a_row = warp_m * 32 + (lane & 15);
    const int a_k8  = lane >> 4;
    const int b_row = warp_n * 64 + (lane & 7) + ((lane >> 4) << 3);
    const int b_k8  = (lane >> 3) & 1;

    float acc[2][8][4];
#pragma unroll
    for (int a = 0; a < 2; a++)
#pragma unroll
        for (int b = 0; b < 8; b++)
#pragma unroll
            for (int cq = 0; cq < 4; cq++) acc[a][b][cq] = 0.0f;

    GEMM_MAINLOOP(Ah + (size_t)m0 * K, Bh + (size_t)n0 * K, K);

    const int crow = m0 + warp_m * 32 + (lane >> 2);
    const int ccol = n0 + warp_n * 64 + (lane & 3) * 2;
#pragma unroll
    for (int j = 0; j < 8; j++) {
        int col = ccol + j * 8;
        float b0 = bias[col], b1 = bias[col + 1];
#pragma unroll
        for (int mt = 0; mt < 2; mt++) {
            int r0 = crow + mt * 16;
            float2 o0 = make_float2(acc[mt][j][0] + b0, acc[mt][j][1] + b1);
            float2 o1 = make_float2(acc[mt][j][2] + b0, acc[mt][j][3] + b1);
            *(float2*)(Cm + (size_t)r0 * N + col)       = o0;
            *(float2*)(Cm + (size_t)(r0 + 8) * N + col) = o1;
        }
    }
}

// ============================================================
// HMMA sliding-window attention (unchanged — R9/R12 version)
// ============================================================
__global__ __launch_bounds__(256) void attn_mma_kernel(
    const __half* __restrict__ qh, const __half* __restrict__ kh,
    const __half* __restrict__ vh, __half* __restrict__ att)
{
    __shared__ __half Qs[2][64 * 64];
    __shared__ __half Ks[2][64 * 64];
    __shared__ __half Vs[2][64 * 64];

    const int t = threadIdx.x, wid = t >> 5, lane = t & 31;
    const int wm = wid & 3, hsel = wid >> 2;
    const int q0 = blockIdx.x * 64;
    const int hp = blockIdx.y;
    const int b  = blockIdx.z;
    const int h  = hp * 2 + hsel;
    const int hk = hp >> 1;

    const __half* Kg = kh + ((size_t)(b * HKVn + hk) * Sn) * 64;
    const __half* Vg = vh + ((size_t)(b * HKVn + hk) * Sn) * 64;

    const uint32_t sQ = smem_u32(Qs[hsel]);
    const uint32_t sK = smem_u32(Ks);
    const uint32_t sV = smem_u32(Vs);

    {
        const uint32_t sQ0 = smem_u32(Qs);
        for (int i = t; i < 1024; i += 256) {
            int hs = i >> 9, row = (i >> 3) & 63, c = i & 7;
            uint32_t sw = (uint32_t)hs * 8192u + (uint32_t)row * 128u +
                          (uint32_t)((c ^ (row & 7)) << 4);
            cp16(sQ0 + sw,
                 qh + (((size_t)(b * Hn + hp * 2 + hs) * Sn) + q0 + row) * 64 + c * 8);
        }
    }

    int lo = 0; while (q0 - 128 + lo * 64 < 0) lo++;
    int hi = 4; while (q0 - 128 + hi * 64 + 64 > Sn) hi--;

#define PREFETCH(it, buf) do { \
    int kb_ = q0 - 128 + (it) * 64; \
    const __half* Kt_ = Kg + (size_t)kb_ * 64; \
    const __half* Vt_ = Vg + (size_t)kb_ * 64; \
    uint32_t sk_ = sK + (uint32_t)(buf) * 8192u; \
    uint32_t sv_ = sV + (uint32_t)(buf) * 8192u; \
    for (int i_ = t; i_ < 512; i_ += 256) { \
        int row_ = i_ >> 3, c_ = i_ & 7; \
        uint32_t sw_ = (uint32_t)row_ * 128u + (uint32_t)((c_ ^ (row_ & 7)) << 4); \
        cp16(sk_ + sw_, Kt_ + row_ * 64 + c_ * 8); \
        cp16(sv_ + sw_, Vt_ + row_ * 64 + c_ * 8); \
    } } while (0)

    PREFETCH(lo, 0);
    CP_COMMIT();

    const int arow = wm * 16 + (lane & 15);
    const int ak8  = lane >> 4;
    const int brow = (lane & 7) + ((lane >> 4) << 3);
    const int bk8  = (lane >> 3) & 1;
    const int vrow = (lane & 7) + (((lane >> 3) & 1) << 3);
    const int vc8  = lane >> 4;

    const int r0g = q0 + wm * 16 + (lane >> 2);
    const int r1g = r0g + 8;

    float acc[8][4];
#pragma unroll
    for (int g = 0; g < 8; g++)
#pragma unroll
        for (int e = 0; e < 4; e++) acc[g][e] = 0.0f;
    float l0 = 0.0f, l1 = 0.0f;

    uint32_t qf[4][4];
    bool qloaded = false;

    for (int it = lo; it <= hi; ++it) {
        const int buf = (it - lo) & 1;
        if (it < hi) { PREFETCH(it + 1, buf ^ 1); CP_COMMIT(); CP_WAIT1(); }
        else { CP_WAIT0(); }
        __syncthreads();

        if (!qloaded) {
#pragma unroll
            for (int kblk = 0; kblk < 4; kblk++) {
                uint32_t ad = sQ + (uint32_t)arow * 128u +
                              (uint32_t)(((kblk * 2 + ak8) ^ (arow & 7)) << 4);
                ldmx4(qf[kblk], ad);
            }
            qloaded = true;
        }

        const int kb = q0 - 128 + it * 64;
        const uint32_t sk = sK + (uint32_t)buf * 8192u;
        const uint32_t sv = sV + (uint32_t)buf * 8192u;
        const bool need_mask = (it == 0) || (it == 4);

        float sc[8][4];
#pragma unroll
        for (int g = 0; g < 8; g++)
#pragma unroll
            for (int e = 0; e < 4; e++) sc[g][e] = 0.0f;
#pragma unroll
        for (int kblk = 0; kblk < 4; kblk++) {
#pragma unroll
            for (int g = 0; g < 4; g++) {
                int r = g * 16 + brow;
                uint32_t bd = sk + (uint32_t)r * 128u +
                              (uint32_t)(((kblk * 2 + bk8) ^ (r & 7)) << 4);
                uint32_t bf[4];
                ldmx4(bf, bd);
                mma16816(sc[2 * g],     qf[kblk], bf);
                mma16816(sc[2 * g + 1], qf[kblk], bf + 2);
            }
        }

        uint32_t pf[8][2];
        if (need_mask) {
#pragma unroll
            for (int g = 0; g < 8; g++) {
                int j0 = kb + g * 8 + (lane & 3) * 2;
                int j1 = j0 + 1;
                float p0 = (abs(j0 - r0g) <= 128) ? ex2f(sc[g][0]) : 0.0f;
                float p1 = (abs(j1 - r0g) <= 128) ? ex2f(sc[g][1]) : 0.0f;
                float p2 = (abs(j0 - r1g) <= 128) ? ex2f(sc[g][2]) : 0.0f;
                float p3 = (abs(j1 - r1g) <= 128) ? ex2f(sc[g][3]) : 0.0f;
                l0 += p0 + p1;
                l1 += p2 + p3;
                pf[g][0] = pack_h2(p0, p1);
                pf[g][1] = pack_h2(p2, p3);
            }
        } else {
#pragma unroll
            for (int g = 0; g < 8; g++) {
                float p0 = ex2f(sc[g][0]);
                float p1 = ex2f(sc[g][1]);
                float p2 = ex2f(sc[g][2]);
                float p3 = ex2f(sc[g][3]);
                l0 += p0 + p1;
                l1 += p2 + p3;
                pf[g][0] = pack_h2(p0, p1);
                pf[g][1] = pack_h2(p2, p3);
            }
        }

#pragma unroll
        for (int jj = 0; jj < 4; jj++) {
            uint32_t a[4] = { pf[2 * jj][0], pf[2 * jj][1],
                              pf[2 * jj + 1][0], pf[2 * jj + 1][1] };
#pragma unroll
            for (int dg = 0; dg < 4; dg++) {
                int r = jj * 16 + vrow;
                uint32_t bd = sv + (uint32_t)r * 128u +
                              (uint32_t)(((dg * 2 + vc8) ^ (r & 7)) << 4);
                uint32_t bf[4];
                ldmx4t(bf, bd);
                mma16816(acc[2 * dg],     a, bf);
                mma16816(acc[2 * dg + 1], a, bf + 2);
            }
        }
        __syncthreads();
    }
#undef PREFETCH

    l0 += __shfl_xor_sync(0xffffffffu, l0, 1);
    l0 += __shfl_xor_sync(0xffffffffu, l0, 2);
    l1 += __shfl_xor_sync(0xffffffffu, l1, 1);
    l1 += __shfl_xor_sync(0xffffffffu, l1, 2);
    const float i0 = 1.0f / l0, i1 = 1.0f / l1;
    const size_t base0 = ((size_t)(b * Sn) + r0g) * (Hn * DHn) + h * 64;
    const size_t base1 = ((size_t)(b * Sn) + r1g) * (Hn * DHn) + h * 64;
#pragma unroll
    for (int g = 0; g < 8; g++) {
        int d = g * 8 + (lane & 3) * 2;
        *(uint32_t*)(att + base0 + d) = pack_h2(acc[g][0] * i0, acc[g][1] * i0);
        *(uint32_t*)(att + base1 + d) = pack_h2(acc[g][2] * i1, acc[g][3] * i1);
    }
}

// ============================================================
extern "C" void kernel_launch(void* const* d_in, const int* in_sizes, int n_in,
                              void* d_out, int out_size)
{
    const float* x    = (const float*)d_in[0];
    const float* Wq   = (const float*)d_in[1];
    const float* bq   = (const float*)d_in[2];
    const float* Wk   = (const float*)d_in[3];
    const float* bk   = (const float*)d_in[4];
    const float* Wv   = (const float*)d_in[5];
    const float* bv   = (const float*)d_in[6];
    const float* Wo   = (const float*)d_in[7];
    const float* bo   = (const float*)d_in[8];
    const float* qn   = (const float*)d_in[9];
    const float* kn   = (const float*)d_in[10];
    const float* cosT = (const float*)d_in[11];
    const float* sinT = (const float*)d_in[12];
    float* out = (float*)d_out;

    __half *xh, *qh, *kh, *vh, *ah, *wqkv, *wo;
    cudaGetSymbolAddress((void**)&xh,   g_xh);
    cudaGetSymbolAddress((void**)&qh,   g_qh);
    cudaGetSymbolAddress((void**)&kh,   g_kh);
    cudaGetSymbolAddress((void**)&vh,   g_vh);
    cudaGetSymbolAddress((void**)&ah,   g_ah);
    cudaGetSymbolAddress((void**)&wqkv, g_wqkv);
    cudaGetSymbolAddress((void**)&wo,   g_wo);

    cudaFuncSetAttribute(mm_qkv_fused_kernel,
                         cudaFuncAttributeMaxDynamicSharedMemorySize, 49152);
    cudaFuncSetAttribute(mm_hmma_kernel,
                         cudaFuncAttributeMaxDynamicSharedMemorySize, 49152);
    const int DSMEM = 49152;

    prep_kernel<<<2560 + 4096, 256>>>(x, Wq, Wk, Wv, Wo, xh, wqkv, wo);

    mm_qkv_fused_kernel<<<dim3(12, 256), 128, DSMEM>>>(
        xh, wqkv, bq, bk, bv, qn, kn, cosT, sinT, qh, kh, vh);

    attn_mma_kernel<<<dim3(Sn / 64, Hn / 2, Bn), 256>>>(qh, kh, vh, ah);

    mm_hmma_kernel<<<dim3(8, 256), 128, DSMEM>>>(ah, wo, bo, out, 1024, 1024);
}

// round 14
// speedup vs baseline: 1.0180x; 1.0180x over previous
#include <cuda_runtime.h>
#include <cuda_fp16.h>
#include <cstdint>

#define Bn   4
#define Sn   4096
#define Dn   1024
#define Hn   16
#define HKVn 4
#define DHn  64
#define Mtok (Bn*Sn)            // 16384

// Q pre-scale: (1/sqrt(64)) * log2(e) so attention can use ex2 directly
#define QSCALE 0.18033688011112042f

// ---- scratch ----
__device__ __half g_xh [Mtok * Dn];
__device__ __half g_qh [Bn * Hn   * Sn * DHn];
__device__ __half g_kh [Bn * HKVn * Sn * DHn];
__device__ __half g_vh [Bn * HKVn * Sn * DHn];
__device__ __half g_ah [Mtok * Hn * DHn];
__device__ __half g_wqkv[1536 * Dn];
__device__ __half g_wo  [Hn * DHn * Dn];

// ============================================================
// helpers
// ============================================================
__device__ __forceinline__ uint32_t smem_u32(const void* p) {
    uint32_t a;
    asm("{ .reg .u64 t; cvta.to.shared.u64 t, %1; cvt.u32.u64 %0, t; }" : "=r"(a) : "l"(p));
    return a;
}
__device__ __forceinline__ void cp16(uint32_t dst, const void* src) {
    asm volatile("cp.async.cg.shared.global [%0], [%1], 16;" :: "r"(dst), "l"(src));
}
#define CP_COMMIT() asm volatile("cp.async.commit_group;" ::: "memory")
#define CP_WAIT0()  asm volatile("cp.async.wait_group 0;" ::: "memory")
#define CP_WAIT1()  asm volatile("cp.async.wait_group 1;" ::: "memory")
#define CP_WAIT4()  asm volatile("cp.async.wait_group 4;" ::: "memory")

__device__ __forceinline__ void ldmx4(uint32_t* r, uint32_t addr) {
    asm volatile("ldmatrix.sync.aligned.m8n8.x4.shared.b16 {%0,%1,%2,%3}, [%4];"
        : "=r"(r[0]), "=r"(r[1]), "=r"(r[2]), "=r"(r[3]) : "r"(addr));
}
__device__ __forceinline__ void ldmx4t(uint32_t* r, uint32_t addr) {
    asm volatile("ldmatrix.sync.aligned.m8n8.x4.trans.shared.b16 {%0,%1,%2,%3}, [%4];"
        : "=r"(r[0]), "=r"(r[1]), "=r"(r[2]), "=r"(r[3]) : "r"(addr));
}
__device__ __forceinline__ void mma16816(float* c, const uint32_t* a, const uint32_t* b) {
    asm volatile("mma.sync.aligned.m16n8k16.row.col.f32.f16.f16.f32 "
        "{%0,%1,%2,%3}, {%4,%5,%6,%7}, {%8,%9}, {%0,%1,%2,%3};"
        : "+f"(c[0]), "+f"(c[1]), "+f"(c[2]), "+f"(c[3])
        : "r"(a[0]), "r"(a[1]), "r"(a[2]), "r"(a[3]), "r"(b[0]), "r"(b[1]));
}
__device__ __forceinline__ uint32_t pack_h2(float a, float b) {
    __half2 h = __floats2half2_rn(a, b);
    return *reinterpret_cast<uint32_t*>(&h);
}
__device__ __forceinline__ float ex2f(float x) {
    float y;
    asm("ex2.approx.ftz.f32 %0, %1;" : "=f"(y) : "f"(x));
    return y;
}

// ============================================================
// merged prep kernel: x fp32->fp16 (MLP=4) + 4 weight transposes
// ============================================================
__global__ __launch_bounds__(256) void prep_kernel(
    const float* __restrict__ x,
    const float* __restrict__ Wq, const float* __restrict__ Wk,
    const float* __restrict__ Wv, const float* __restrict__ Wo,
    __half* __restrict__ xh, __half* __restrict__ wqkv, __half* __restrict__ wo)
{
    const int bid = blockIdx.x;
    const int t = threadIdx.x;

    if (bid >= 2560) {
        int base = (bid - 2560) * 1024 + t;
        float4 v[4];
#pragma unroll
        for (int u = 0; u < 4; u++) v[u] = ((const float4*)x)[base + u * 256];
#pragma unroll
        for (int u = 0; u < 4; u++) {
            ushort4 o;
            o.x = __half_as_ushort(__float2half_rn(v[u].x));
            o.y = __half_as_ushort(__float2half_rn(v[u].y));
            o.z = __half_as_ushort(__float2half_rn(v[u].z));
            o.w = __half_as_ushort(__float2half_rn(v[u].w));
            ((ushort4*)xh)[base + u * 256] = o;
        }
        return;
    }

    __shared__ float tile[32][33];
    const float* W;
    __half* dst;
    int N, base;
    if (bid < 1024)      { W = Wq; dst = wqkv;               N = 1024; base = bid; }
    else if (bid < 1280) { W = Wk; dst = wqkv + 1024 * 1024; N = 256;  base = bid - 1024; }
    else if (bid < 1536) { W = Wv; dst = wqkv + 1280 * 1024; N = 256;  base = bid - 1280; }
    else                 { W = Wo; dst = wo;                 N = 1024; base = bid - 1536; }

    const int nblk = N >> 5;
    const int n0 = (base % nblk) * 32;
    const int k0 = (base / nblk) * 32;
    const int tx = t & 31, ty = t >> 5;

    for (int r = ty; r < 32; r += 8)
        tile[r][tx] = W[(size_t)(k0 + r) * N + n0 + tx];
    __syncthreads();
    for (int r = ty; r < 32; r += 8)
        dst[(size_t)(n0 + r) * 1024 + k0 + tx] = __float2half_rn(tile[tx][r]);
}

// ============================================================
// GEMM mainloop: 128x128 CTA tile, 4 warps, 64x64 warp tile.
// BK=32, 6-stage cp.async ring (16KB/stage, 96KB), wait_group 4,
// 2 chunks per sync window. 2 CTAs/SM.
// ============================================================
#define STAGE_LOAD_CH(buf, c) do { \
    uint32_t sb_ = sbase + (uint32_t)(buf) * 16384u; \
    _Pragma("unroll") \
    for (int i_ = 0; i_ < 4; i_++) { \
        int idx_ = t + i_ * 128; \
        int row_ = idx_ >> 2; \
        int lc_  = idx_ & 3; \
        uint32_t sw_ = (uint32_t)row_ * 64u + (uint32_t)((lc_ ^ ((row_ >> 1) & 3)) << 4); \
        size_t go_ = (size_t)row_ * (size_t)Kd + (size_t)(c) * 32 + lc_ * 8; \
        cp16(sb_ + sw_,         gA + go_); \
        cp16(sb_ + 8192u + sw_, gB + go_); \
    } } while (0)

#define GEMM_COMPUTE_CH(buf) do { \
    const uint32_t sb = sbase + (uint32_t)(buf) * 16384u; \
    _Pragma("unroll") \
    for (int ks = 0; ks < 2; ks++) { \
        uint32_t ahf[4][4], bhf[4][4]; \
        _Pragma("unroll") \
        for (int mt = 0; mt < 4; mt++) { \
            int r = a_row + mt * 16; \
            uint32_t ad = sb + (uint32_t)r * 64u + \
                          (uint32_t)(((ks * 2 + a_k8) ^ ((r >> 1) & 3)) << 4); \
            ldmx4(ahf[mt], ad); \
        } \
        _Pragma("unroll") \
        for (int g = 0; g < 4; g++) { \
            int r = b_row + g * 16; \
            uint32_t bd = sb + 8192u + (uint32_t)r * 64u + \
                          (uint32_t)(((ks * 2 + b_k8) ^ ((r >> 1) & 3)) << 4); \
            ldmx4(bhf[g], bd); \
        } \
        _Pragma("unroll") \
        for (int mt = 0; mt < 4; mt++) \
            _Pragma("unroll") \
            for (int j = 0; j < 8; j++) \
                mma16816(acc[mt][j], ahf[mt], &bhf[j >> 1][(j & 1) * 2]); \
    } } while (0)

#define GEMM_MAINLOOP(Agl, Bgl, Kdim) do { \
    const __half* gA = (Agl); \
    const __half* gB = (Bgl); \
    const int Kd = (Kdim); \
    const int NCH = Kd >> 5; \
    _Pragma("unroll") \
    for (int s = 0; s < 6; s++) { STAGE_LOAD_CH(s, s); CP_COMMIT(); } \
    int b0 = 0; \
    for (int c = 0; c < NCH; c += 2) { \
        CP_WAIT4(); \
        __syncthreads(); \
        int b1 = (b0 == 5) ? 0 : b0 + 1; \
        GEMM_COMPUTE_CH(b0); \
        GEMM_COMPUTE_CH(b1); \
        __syncthreads(); \
        if (c + 6 < NCH) STAGE_LOAD_CH(b0, c + 6); \
        CP_COMMIT(); \
        if (c + 7 < NCH) STAGE_LOAD_CH(b1, c + 7); \
        CP_COMMIT(); \
        b0 = (b1 == 5) ? 0 : b1 + 1; \
    } } while (0)

// ============================================================
// Fused QKV GEMM + bias + RMSNorm + RoPE + fp16 transpose store.
// ============================================================
__global__ __launch_bounds__(128, 2) void mm_qkv_fused_kernel(
    const __half* __restrict__ Ah, const __half* __restrict__ Bw,
    const float* __restrict__ bq, const float* __restrict__ bk,
    const float* __restrict__ bv,
    const float* __restrict__ qnw, const float* __restrict__ knw,
    const float* __restrict__ cosT, const float* __restrict__ sinT,
    __half* __restrict__ qh, __half* __restrict__ kh, __half* __restrict__ vh)
{
    extern __shared__ char sm[];
    const int t = threadIdx.x, wid = t >> 5, lane = t & 31;
    const int m0 = blockIdx.y * 128, n0 = blockIdx.x * 128;
    const uint32_t sbase = smem_u32(sm);

    const int warp_m = wid & 1;
    const int warp_n = wid >> 1;
    const int a_row = warp_m * 64 + (lane & 15);
    const int a_k8  = lane >> 4;
    const int b_row = warp_n * 64 + (lane & 7) + ((lane >> 4) << 3);
    const int b_k8  = (lane >> 3) & 1;

    float acc[4][8][4];
#pragma unroll
    for (int a = 0; a < 4; a++)
#pragma unroll
        for (int b = 0; b < 8; b++)
#pragma unroll
            for (int cq = 0; cq < 4; cq++) acc[a][b][cq] = 0.0f;

    GEMM_MAINLOOP(Ah + (size_t)m0 * Dn, Bw + (size_t)n0 * Dn, Dn);

    const int gc = n0 + warp_n * 64;
    const int q2 = (lane & 3) * 2;

    int mode, hh, NHd;
    __half* dst;
    const float* bptr;
    const float* wn = qnw;
    if (gc < 1024)      { mode = 0; hh = gc >> 6;          dst = qh; bptr = bq + gc;          wn = qnw; NHd = Hn;  }
    else if (gc < 1280) { mode = 1; hh = (gc - 1024) >> 6; dst = kh; bptr = bk + (gc - 1024); wn = knw; NHd = HKVn; }
    else                { mode = 2; hh = (gc - 1280) >> 6; dst = vh; bptr = bv + (gc - 1280); NHd = HKVn; }

    float bvv[8][2], wnv[8][2];
#pragma unroll
    for (int j = 0; j < 8; j++) {
        bvv[j][0] = bptr[j * 8 + q2];
        bvv[j][1] = bptr[j * 8 + q2 + 1];
    }
    if (mode < 2) {
#pragma unroll
        for (int j = 0; j < 8; j++) {
            wnv[j][0] = wn[j * 8 + q2];
            wnv[j][1] = wn[j * 8 + q2 + 1];
        }
    }

#pragma unroll
    for (int mt = 0; mt < 4; mt++) {
#pragma unroll
        for (int pr = 0; pr < 2; pr++) {
            const int row = m0 + warp_m * 64 + (lane >> 2) + mt * 16 + pr * 8;
            const int s  = row & (Sn - 1);
            const int bb = row >> 12;
            float v[8][2];
#pragma unroll
            for (int j = 0; j < 8; j++) {
                v[j][0] = acc[mt][j][pr * 2]     + bvv[j][0];
                v[j][1] = acc[mt][j][pr * 2 + 1] + bvv[j][1];
            }
            if (mode < 2) {
                float ss = 0.0f;
#pragma unroll
                for (int j = 0; j < 8; j++) ss += v[j][0] * v[j][0] + v[j][1] * v[j][1];
                ss += __shfl_xor_sync(0xffffffffu, ss, 1);
                ss += __shfl_xor_sync(0xffffffffu, ss, 2);
                float r = rsqrtf(ss * (1.0f / 64.0f) + 1e-6f);
#pragma unroll
                for (int j = 0; j < 8; j++) {
                    v[j][0] *= r * wnv[j][0];
                    v[j][1] *= r * wnv[j][1];
                }
                const float* cr = cosT + s * 64;
                const float* sr = sinT + s * 64;
#pragma unroll
                for (int j = 0; j < 4; j++) {
#pragma unroll
                    for (int p = 0; p < 2; p++) {
                        int d = j * 8 + q2 + p;
                        float x0 = v[j][p], x1 = v[j + 4][p];
                        v[j][p]     = x0 * cr[d]      - x1 * sr[d];
                        v[j + 4][p] = x1 * cr[d + 32] + x0 * sr[d + 32];
                    }
                }
                if (mode == 0) {
#pragma unroll
                    for (int j = 0; j < 8; j++) { v[j][0] *= QSCALE; v[j][1] *= QSCALE; }
                }
            }
            __half* dp = dst + (((size_t)(bb * NHd + hh)) * Sn + s) * 64;
#pragma unroll
            for (int j = 0; j < 8; j++)
                *(uint32_t*)(dp + j * 8 + q2) = pack_h2(v[j][0], v[j][1]);
        }
    }
}

// ============================================================
// Standard HMMA GEMM (O-projection): f32 accumulate
// ============================================================
__global__ __launch_bounds__(128, 2) void mm_hmma_kernel(
    const __half* __restrict__ Ah, const __half* __restrict__ Bh,
    const float* __restrict__ bias, float* __restrict__ Cm, int N, int K)
{
    extern __shared__ char sm[];
    const int t = threadIdx.x, wid = t >> 5, lane = t & 31;
    const int m0 = blockIdx.y * 128, n0 = blockIdx.x * 128;
    const uint32_t sbase = smem_u32(sm);

    const int warp_m = wid & 1;
    const int warp_n = wid >> 1;
    const int a_row = warp_m * 64 + (lane & 15);
    const int a_k8  = lane >> 4;
    const int b_row = warp_n * 64 + (lane & 7) + ((lane >> 4) << 3);
    const int b_k8  = (lane >> 3) & 1;

    float acc[4][8][4];
#pragma unroll
    for (int a = 0; a < 4; a++)
#pragma unroll
        for (int b = 0; b < 8; b++)
#pragma unroll
            for (int cq = 0; cq < 4; cq++) acc[a][b][cq] = 0.0f;

    GEMM_MAINLOOP(Ah + (size_t)m0 * K, Bh + (size_t)n0 * K, K);

    const int crow = m0 + warp_m * 64 + (lane >> 2);
    const int ccol = n0 + warp_n * 64 + (lane & 3) * 2;
#pragma unroll
    for (int j = 0; j < 8; j++) {
        int col = ccol + j * 8;
        float b0 = bias[col], b1 = bias[col + 1];
#pragma unroll
        for (int mt = 0; mt < 4; mt++) {
            int r0 = crow + mt * 16;
            float2 o0 = make_float2(acc[mt][j][0] + b0, acc[mt][j][1] + b1);
            float2 o1 = make_float2(acc[mt][j][2] + b0, acc[mt][j][3] + b1);
            *(float2*)(Cm + (size_t)r0 * N + col)       = o0;
            *(float2*)(Cm + (size_t)(r0 + 8) * N + col) = o1;
        }
    }
}

// ============================================================
// HMMA sliding-window attention (R12 version)
// ============================================================
__global__ __launch_bounds__(256) void attn_mma_kernel(
    const __half* __restrict__ qh, const __half* __restrict__ kh,
    const __half* __restrict__ vh, __half* __restrict__ att)
{
    __shared__ __half Qs[2][64 * 64];
    __shared__ __half Ks[2][64 * 64];
    __shared__ __half Vs[2][64 * 64];

    const int t = threadIdx.x, wid = t >> 5, lane = t & 31;
    const int wm = wid & 3, hsel = wid >> 2;
    const int q0 = blockIdx.x * 64;
    const int hp = blockIdx.y;
    const int b  = blockIdx.z;
    const int h  = hp * 2 + hsel;
    const int hk = hp >> 1;

    const __half* Kg = kh + ((size_t)(b * HKVn + hk) * Sn) * 64;
    const __half* Vg = vh + ((size_t)(b * HKVn + hk) * Sn) * 64;

    const uint32_t sQ = smem_u32(Qs[hsel]);
    const uint32_t sK = smem_u32(Ks);
    const uint32_t sV = smem_u32(Vs);

    {
        const uint32_t sQ0 = smem_u32(Qs);
        for (int i = t; i < 1024; i += 256) {
            int hs = i >> 9, row = (i >> 3) & 63, c = i & 7;
            uint32_t sw = (uint32_t)hs * 8192u + (uint32_t)row * 128u +
                          (uint32_t)((c ^ (row & 7)) << 4);
            cp16(sQ0 + sw,
                 qh + (((size_t)(b * Hn + hp * 2 + hs) * Sn) + q0 + row) * 64 + c * 8);
        }
    }

    int lo = 0; while (q0 - 128 + lo * 64 < 0) lo++;
    int hi = 4; while (q0 - 128 + hi * 64 + 64 > Sn) hi--;

#define PREFETCH(it, buf) do { \
    int kb_ = q0 - 128 + (it) * 64; \
    const __half* Kt_ = Kg + (size_t)kb_ * 64; \
    const __half* Vt_ = Vg + (size_t)kb_ * 64; \
    uint32_t sk_ = sK + (uint32_t)(buf) * 8192u; \
    uint32_t sv_ = sV + (uint32_t)(buf) * 8192u; \
    for (int i_ = t; i_ < 512; i_ += 256) { \
        int row_ = i_ >> 3, c_ = i_ & 7; \
        uint32_t sw_ = (uint32_t)row_ * 128u + (uint32_t)((c_ ^ (row_ & 7)) << 4); \
        cp16(sk_ + sw_, Kt_ + row_ * 64 + c_ * 8); \
        cp16(sv_ + sw_, Vt_ + row_ * 64 + c_ * 8); \
    } } while (0)

    PREFETCH(lo, 0);
    CP_COMMIT();

    const int arow = wm * 16 + (lane & 15);
    const int ak8  = lane >> 4;
    const int brow = (lane & 7) + ((lane >> 4) << 3);
    const int bk8  = (lane >> 3) & 1;
    const int vrow = (lane & 7) + (((lane >> 3) & 1) << 3);
    const int vc8  = lane >> 4;

    const int r0g = q0 + wm * 16 + (lane >> 2);
    const int r1g = r0g + 8;

    float acc[8][4];
#pragma unroll
    for (int g = 0; g < 8; g++)
#pragma unroll
        for (int e = 0; e < 4; e++) acc[g][e] = 0.0f;
    float l0 = 0.0f, l1 = 0.0f;

    uint32_t qf[4][4];
    bool qloaded = false;

    for (int it = lo; it <= hi; ++it) {
        const int buf = (it - lo) & 1;
        if (it < hi) { PREFETCH(it + 1, buf ^ 1); CP_COMMIT(); CP_WAIT1(); }
        else { CP_WAIT0(); }
        __syncthreads();

        if (!qloaded) {
#pragma unroll
            for (int kblk = 0; kblk < 4; kblk++) {
                uint32_t ad = sQ + (uint32_t)arow * 128u +
                              (uint32_t)(((kblk * 2 + ak8) ^ (arow & 7)) << 4);
                ldmx4(qf[kblk], ad);
            }
            qloaded = true;
        }

        const int kb = q0 - 128 + it * 64;
        const uint32_t sk = sK + (uint32_t)buf * 8192u;
        const uint32_t sv = sV + (uint32_t)buf * 8192u;
        const bool need_mask = (it == 0) || (it == 4);

        float sc[8][4];
#pragma unroll
        for (int g = 0; g < 8; g++)
#pragma unroll
            for (int e = 0; e < 4; e++) sc[g][e] = 0.0f;
#pragma unroll
        for (int kblk = 0; kblk < 4; kblk++) {
#pragma unroll
            for (int g = 0; g < 4; g++) {
                int r = g * 16 + brow;
                uint32_t bd = sk + (uint32_t)r * 128u +
                              (uint32_t)(((kblk * 2 + bk8) ^ (r & 7)) << 4);
                uint32_t bf[4];
                ldmx4(bf, bd);
                mma16816(sc[2 * g],     qf[kblk], bf);
                mma16816(sc[2 * g + 1], qf[kblk], bf + 2);
            }
        }

        uint32_t pf[8][2];
        if (need_mask) {
#pragma unroll
            for (int g = 0; g < 8; g++) {
                int j0 = kb + g * 8 + (lane & 3) * 2;
                int j1 = j0 + 1;
                float p0 = (abs(j0 - r0g) <= 128) ? ex2f(sc[g][0]) : 0.0f;
                float p1 = (abs(j1 - r0g) <= 128) ? ex2f(sc[g][1]) : 0.0f;
                float p2 = (abs(j0 - r1g) <= 128) ? ex2f(sc[g][2]) : 0.0f;
                float p3 = (abs(j1 - r1g) <= 128) ? ex2f(sc[g][3]) : 0.0f;
                l0 += p0 + p1;
                l1 += p2 + p3;
                pf[g][0] = pack_h2(p0, p1);
                pf[g][1] = pack_h2(p2, p3);
            }
        } else {
#pragma unroll
            for (int g = 0; g < 8; g++) {
                float p0 = ex2f(sc[g][0]);
                float p1 = ex2f(sc[g][1]);
                float p2 = ex2f(sc[g][2]);
                float p3 = ex2f(sc[g][3]);
                l0 += p0 + p1;
                l1 += p2 + p3;
                pf[g][0] = pack_h2(p0, p1);
                pf[g][1] = pack_h2(p2, p3);
            }
        }

#pragma unroll
        for (int jj = 0; jj < 4; jj++) {
            uint32_t a[4] = { pf[2 * jj][0], pf[2 * jj][1],
                              pf[2 * jj + 1][0], pf[2 * jj + 1][1] };
#pragma unroll
            for (int dg = 0; dg < 4; dg++) {
                int r = jj * 16 + vrow;
                uint32_t bd = sv + (uint32_t)r * 128u +
                              (uint32_t)(((dg * 2 + vc8) ^ (r & 7)) << 4);
                uint32_t bf[4];
                ldmx4t(bf, bd);
                mma16816(acc[2 * dg],     a, bf);
                mma16816(acc[2 * dg + 1], a, bf + 2);
            }
        }
        __syncthreads();
    }
#undef PREFETCH

    l0 += __shfl_xor_sync(0xffffffffu, l0, 1);
    l0 += __shfl_xor_sync(0xffffffffu, l0, 2);
    l1 += __shfl_xor_sync(0xffffffffu, l1, 1);
    l1 += __shfl_xor_sync(0xffffffffu, l1, 2);
    const float i0 = 1.0f / l0, i1 = 1.0f / l1;
    const size_t base0 = ((size_t)(b * Sn) + r0g) * (Hn * DHn) + h * 64;
    const size_t base1 = ((size_t)(b * Sn) + r1g) * (Hn * DHn) + h * 64;
#pragma unroll
    for (int g = 0; g < 8; g++) {
        int d = g * 8 + (lane & 3) * 2;
        *(uint32_t*)(att + base0 + d) = pack_h2(acc[g][0] * i0, acc[g][1] * i0);
        *(uint32_t*)(att + base1 + d) = pack_h2(acc[g][2] * i1, acc[g][3] * i1);
    }
}

// ============================================================
extern "C" void kernel_launch(void* const* d_in, const int* in_sizes, int n_in,
                              void* d_out, int out_size)
{
    const float* x    = (const float*)d_in[0];
    const float* Wq   = (const float*)d_in[1];
    const float* bq   = (const float*)d_in[2];
    const float* Wk   = (const float*)d_in[3];
    const float* bk   = (const float*)d_in[4];
    const float* Wv   = (const float*)d_in[5];
    const float* bv   = (const float*)d_in[6];
    const float* Wo   = (const float*)d_in[7];
    const float* bo   = (const float*)d_in[8];
    const float* qn   = (const float*)d_in[9];
    const float* kn   = (const float*)d_in[10];
    const float* cosT = (const float*)d_in[11];
    const float* sinT = (const float*)d_in[12];
    float* out = (float*)d_out;

    __half *xh, *qh, *kh, *vh, *ah, *wqkv, *wo;
    cudaGetSymbolAddress((void**)&xh,   g_xh);
    cudaGetSymbolAddress((void**)&qh,   g_qh);
    cudaGetSymbolAddress((void**)&kh,   g_kh);
    cudaGetSymbolAddress((void**)&vh,   g_vh);
    cudaGetSymbolAddress((void**)&ah,   g_ah);
    cudaGetSymbolAddress((void**)&wqkv, g_wqkv);
    cudaGetSymbolAddress((void**)&wo,   g_wo);

    cudaFuncSetAttribute(mm_qkv_fused_kernel,
                         cudaFuncAttributeMaxDynamicSharedMemorySize, 98304);
    cudaFuncSetAttribute(mm_hmma_kernel,
                         cudaFuncAttributeMaxDynamicSharedMemorySize, 98304);
    const int DSMEM = 98304;

    prep_kernel<<<2560 + 4096, 256>>>(x, Wq, Wk, Wv, Wo, xh, wqkv, wo);

    mm_qkv_fused_kernel<<<dim3(12, 128), 128, DSMEM>>>(
        xh, wqkv, bq, bk, bv, qn, kn, cosT, sinT, qh, kh, vh);

    attn_mma_kernel<<<dim3(Sn / 64, Hn / 2, Bn), 256>>>(qh, kh, vh, ah);

    mm_hmma_kernel<<<dim3(8, 128), 128, DSMEM>>>(ah, wo, bo, out, 1024, 1024);
}

// round 15
// speedup vs baseline: 1.0280x; 1.0099x over previous
#include <cuda_runtime.h>
#include <cuda_fp16.h>
#include <cstdint>

#define Bn   4
#define Sn   4096
#define Dn   1024
#define Hn   16
#define HKVn 4
#define DHn  64
#define Mtok (Bn*Sn)            // 16384

// Q pre-scale: (1/sqrt(64)) * log2(e) so attention can use ex2 directly
#define QSCALE 0.18033688011112042f

// ---- scratch ----
__device__ __half g_xh [Mtok * Dn];
__device__ __half g_qh [Bn * Hn   * Sn * DHn];
__device__ __half g_kh [Bn * HKVn * Sn * DHn];
__device__ __half g_vh [Bn * HKVn * Sn * DHn];
__device__ __half g_ah [Mtok * Hn * DHn];
__device__ __half g_wqkv[1536 * Dn];
__device__ __half g_wo  [Hn * DHn * Dn];

// ============================================================
// helpers
// ============================================================
__device__ __forceinline__ uint32_t smem_u32(const void* p) {
    uint32_t a;
    asm("{ .reg .u64 t; cvta.to.shared.u64 t, %1; cvt.u32.u64 %0, t; }" : "=r"(a) : "l"(p));
    return a;
}
__device__ __forceinline__ void cp16(uint32_t dst, const void* src) {
    asm volatile("cp.async.cg.shared.global [%0], [%1], 16;" :: "r"(dst), "l"(src));
}
#define CP_COMMIT() asm volatile("cp.async.commit_group;" ::: "memory")
#define CP_WAIT0()  asm volatile("cp.async.wait_group 0;" ::: "memory")
#define CP_WAIT1()  asm volatile("cp.async.wait_group 1;" ::: "memory")
#define CP_WAIT2()  asm volatile("cp.async.wait_group 2;" ::: "memory")

__device__ __forceinline__ void ldmx4(uint32_t* r, uint32_t addr) {
    asm volatile("ldmatrix.sync.aligned.m8n8.x4.shared.b16 {%0,%1,%2,%3}, [%4];"
        : "=r"(r[0]), "=r"(r[1]), "=r"(r[2]), "=r"(r[3]) : "r"(addr));
}
__device__ __forceinline__ void ldmx4t(uint32_t* r, uint32_t addr) {
    asm volatile("ldmatrix.sync.aligned.m8n8.x4.trans.shared.b16 {%0,%1,%2,%3}, [%4];"
        : "=r"(r[0]), "=r"(r[1]), "=r"(r[2]), "=r"(r[3]) : "r"(addr));
}
__device__ __forceinline__ void mma16816(float* c, const uint32_t* a, const uint32_t* b) {
    asm volatile("mma.sync.aligned.m16n8k16.row.col.f32.f16.f16.f32 "
        "{%0,%1,%2,%3}, {%4,%5,%6,%7}, {%8,%9}, {%0,%1,%2,%3};"
        : "+f"(c[0]), "+f"(c[1]), "+f"(c[2]), "+f"(c[3])
        : "r"(a[0]), "r"(a[1]), "r"(a[2]), "r"(a[3]), "r"(b[0]), "r"(b[1]));
}
__device__ __forceinline__ uint32_t pack_h2(float a, float b) {
    __half2 h = __floats2half2_rn(a, b);
    return *reinterpret_cast<uint32_t*>(&h);
}
__device__ __forceinline__ float ex2f(float x) {
    float y;
    asm("ex2.approx.ftz.f32 %0, %1;" : "=f"(y) : "f"(x));
    return y;
}

// ============================================================
// merged prep kernel: x fp32->fp16 (MLP=4) + 4 weight transposes (unrolled)
// blocks [0,1024): Wq, [1024,1280): Wk, [1280,1536): Wv,
// [1536,2560): Wo, [2560, 2560+4096): x convert
// ============================================================
__global__ __launch_bounds__(256) void prep_kernel(
    const float* __restrict__ x,
    const float* __restrict__ Wq, const float* __restrict__ Wk,
    const float* __restrict__ Wv, const float* __restrict__ Wo,
    __half* __restrict__ xh, __half* __restrict__ wqkv, __half* __restrict__ wo)
{
    const int bid = blockIdx.x;
    const int t = threadIdx.x;

    if (bid >= 2560) {
        int base = (bid - 2560) * 1024 + t;
        float4 v[4];
#pragma unroll
        for (int u = 0; u < 4; u++) v[u] = ((const float4*)x)[base + u * 256];
#pragma unroll
        for (int u = 0; u < 4; u++) {
            ushort4 o;
            o.x = __half_as_ushort(__float2half_rn(v[u].x));
            o.y = __half_as_ushort(__float2half_rn(v[u].y));
            o.z = __half_as_ushort(__float2half_rn(v[u].z));
            o.w = __half_as_ushort(__float2half_rn(v[u].w));
            ((ushort4*)xh)[base + u * 256] = o;
        }
        return;
    }

    __shared__ float tile[32][33];
    const float* W;
    __half* dst;
    int N, base;
    if (bid < 1024)      { W = Wq; dst = wqkv;               N = 1024; base = bid; }
    else if (bid < 1280) { W = Wk; dst = wqkv + 1024 * 1024; N = 256;  base = bid - 1024; }
    else if (bid < 1536) { W = Wv; dst = wqkv + 1280 * 1024; N = 256;  base = bid - 1280; }
    else                 { W = Wo; dst = wo;                 N = 1024; base = bid - 1536; }

    const int nblk = N >> 5;
    const int n0 = (base % nblk) * 32;
    const int k0 = (base / nblk) * 32;
    const int tx = t & 31, ty = t >> 5;

#pragma unroll
    for (int rr = 0; rr < 4; rr++) {
        int r = ty + rr * 8;
        tile[r][tx] = W[(size_t)(k0 + r) * N + n0 + tx];
    }
    __syncthreads();
#pragma unroll
    for (int rr = 0; rr < 4; rr++) {
        int r = ty + rr * 8;
        dst[(size_t)(n0 + r) * 1024 + k0 + tx] = __float2half_rn(tile[tx][r]);
    }
}

// ============================================================
// GEMM mainloop: 128x128 CTA tile, 4 warps, 64x64 warp tile.
// BK=32, 4-stage cp.async ring, 2 chunks per sync window.
// (R12 configuration — f32 accumulate, no branches)
// ============================================================
#define STAGE_LOAD_CH(buf, c) do { \
    uint32_t sb_ = sbase + (uint32_t)(buf) * 16384u; \
    _Pragma("unroll") \
    for (int i_ = 0; i_ < 4; i_++) { \
        int idx_ = t + i_ * 128; \
        int row_ = idx_ >> 2; \
        int lc_  = idx_ & 3; \
        uint32_t sw_ = (uint32_t)row_ * 64u + (uint32_t)((lc_ ^ ((row_ >> 1) & 3)) << 4); \
        size_t go_ = (size_t)row_ * (size_t)Kd + (size_t)(c) * 32 + lc_ * 8; \
        cp16(sb_ + sw_,         gA + go_); \
        cp16(sb_ + 8192u + sw_, gB + go_); \
    } } while (0)

#define GEMM_COMPUTE_CH(cc) do { \
    const uint32_t sb = sbase + (uint32_t)((cc) & 3) * 16384u; \
    _Pragma("unroll") \
    for (int ks = 0; ks < 2; ks++) { \
        uint32_t ahf[4][4], bhf[4][4]; \
        _Pragma("unroll") \
        for (int mt = 0; mt < 4; mt++) { \
            int r = a_row + mt * 16; \
            uint32_t ad = sb + (uint32_t)r * 64u + \
                          (uint32_t)(((ks * 2 + a_k8) ^ ((r >> 1) & 3)) << 4); \
            ldmx4(ahf[mt], ad); \
        } \
        _Pragma("unroll") \
        for (int g = 0; g < 4; g++) { \
            int r = b_row + g * 16; \
            uint32_t bd = sb + 8192u + (uint32_t)r * 64u + \
                          (uint32_t)(((ks * 2 + b_k8) ^ ((r >> 1) & 3)) << 4); \
            ldmx4(bhf[g], bd); \
        } \
        _Pragma("unroll") \
        for (int mt = 0; mt < 4; mt++) \
            _Pragma("unroll") \
            for (int j = 0; j < 8; j++) \
                mma16816(acc[mt][j], ahf[mt], &bhf[j >> 1][(j & 1) * 2]); \
    } } while (0)

#define GEMM_MAINLOOP(Agl, Bgl, Kdim) do { \
    const __half* gA = (Agl); \
    const __half* gB = (Bgl); \
    const int Kd = (Kdim); \
    const int NCH = Kd >> 5; \
    _Pragma("unroll") \
    for (int s = 0; s < 4; s++) { STAGE_LOAD_CH(s, s); CP_COMMIT(); } \
    for (int c = 0; c < NCH; c += 2) { \
        CP_WAIT2(); \
        __syncthreads(); \
        GEMM_COMPUTE_CH(c); \
        GEMM_COMPUTE_CH(c + 1); \
        __syncthreads(); \
        if (c + 4 < NCH) STAGE_LOAD_CH(c & 3, c + 4); \
        CP_COMMIT(); \
        if (c + 5 < NCH) STAGE_LOAD_CH((c + 1) & 3, c + 5); \
        CP_COMMIT(); \
    } } while (0)

// ============================================================
// Fused QKV GEMM + bias + RMSNorm + RoPE + fp16 transpose store.
// ============================================================
__global__ __launch_bounds__(128, 2) void mm_qkv_fused_kernel(
    const __half* __restrict__ Ah, const __half* __restrict__ Bw,
    const float* __restrict__ bq, const float* __restrict__ bk,
    const float* __restrict__ bv,
    const float* __restrict__ qnw, const float* __restrict__ knw,
    const float* __restrict__ cosT, const float* __restrict__ sinT,
    __half* __restrict__ qh, __half* __restrict__ kh, __half* __restrict__ vh)
{
    extern __shared__ char sm[];
    const int t = threadIdx.x, wid = t >> 5, lane = t & 31;
    const int m0 = blockIdx.y * 128, n0 = blockIdx.x * 128;
    const uint32_t sbase = smem_u32(sm);

    const int warp_m = wid & 1;
    const int warp_n = wid >> 1;
    const int a_row = warp_m * 64 + (lane & 15);
    const int a_k8  = lane >> 4;
    const int b_row = warp_n * 64 + (lane & 7) + ((lane >> 4) << 3);
    const int b_k8  = (lane >> 3) & 1;

    float acc[4][8][4];
#pragma unroll
    for (int a = 0; a < 4; a++)
#pragma unroll
        for (int b = 0; b < 8; b++)
#pragma unroll
            for (int cq = 0; cq < 4; cq++) acc[a][b][cq] = 0.0f;

    GEMM_MAINLOOP(Ah + (size_t)m0 * Dn, Bw + (size_t)n0 * Dn, Dn);

    const int gc = n0 + warp_n * 64;
    const int q2 = (lane & 3) * 2;

    int mode, hh, NHd;
    __half* dst;
    const float* bptr;
    const float* wn = qnw;
    if (gc < 1024)      { mode = 0; hh = gc >> 6;          dst = qh; bptr = bq + gc;          wn = qnw; NHd = Hn;  }
    else if (gc < 1280) { mode = 1; hh = (gc - 1024) >> 6; dst = kh; bptr = bk + (gc - 1024); wn = knw; NHd = HKVn; }
    else                { mode = 2; hh = (gc - 1280) >> 6; dst = vh; bptr = bv + (gc - 1280); NHd = HKVn; }

    float bvv[8][2], wnv[8][2];
#pragma unroll
    for (int j = 0; j < 8; j++) {
        bvv[j][0] = bptr[j * 8 + q2];
        bvv[j][1] = bptr[j * 8 + q2 + 1];
    }
    if (mode < 2) {
#pragma unroll
        for (int j = 0; j < 8; j++) {
            wnv[j][0] = wn[j * 8 + q2];
            wnv[j][1] = wn[j * 8 + q2 + 1];
        }
    }

#pragma unroll
    for (int mt = 0; mt < 4; mt++) {
#pragma unroll
        for (int pr = 0; pr < 2; pr++) {
            const int row = m0 + warp_m * 64 + (lane >> 2) + mt * 16 + pr * 8;
            const int s  = row & (Sn - 1);
            const int bb = row >> 12;
            float v[8][2];
#pragma unroll
            for (int j = 0; j < 8; j++) {
                v[j][0] = acc[mt][j][pr * 2]     + bvv[j][0];
                v[j][1] = acc[mt][j][pr * 2 + 1] + bvv[j][1];
            }
            if (mode < 2) {
                float ss = 0.0f;
#pragma unroll
                for (int j = 0; j < 8; j++) ss += v[j][0] * v[j][0] + v[j][1] * v[j][1];
                ss += __shfl_xor_sync(0xffffffffu, ss, 1);
                ss += __shfl_xor_sync(0xffffffffu, ss, 2);
                float r = rsqrtf(ss * (1.0f / 64.0f) + 1e-6f);
#pragma unroll
                for (int j = 0; j < 8; j++) {
                    v[j][0] *= r * wnv[j][0];
                    v[j][1] *= r * wnv[j][1];
                }
                const float* cr = cosT + s * 64;
                const float* sr = sinT + s * 64;
#pragma unroll
                for (int j = 0; j < 4; j++) {
#pragma unroll
                    for (int p = 0; p < 2; p++) {
                        int d = j * 8 + q2 + p;
                        float x0 = v[j][p], x1 = v[j + 4][p];
                        v[j][p]     = x0 * cr[d]      - x1 * sr[d];
                        v[j + 4][p] = x1 * cr[d + 32] + x0 * sr[d + 32];
                    }
                }
                if (mode == 0) {
#pragma unroll
                    for (int j = 0; j < 8; j++) { v[j][0] *= QSCALE; v[j][1] *= QSCALE; }
                }
            }
            __half* dp = dst + (((size_t)(bb * NHd + hh)) * Sn + s) * 64;
#pragma unroll
            for (int j = 0; j < 8; j++)
                *(uint32_t*)(dp + j * 8 + q2) = pack_h2(v[j][0], v[j][1]);
        }
    }
}

// ============================================================
// Standard HMMA GEMM (O-projection): f32 accumulate
// ============================================================
__global__ __launch_bounds__(128, 2) void mm_hmma_kernel(
    const __half* __restrict__ Ah, const __half* __restrict__ Bh,
    const float* __restrict__ bias, float* __restrict__ Cm, int N, int K)
{
    extern __shared__ char sm[];
    const int t = threadIdx.x, wid = t >> 5, lane = t & 31;
    const int m0 = blockIdx.y * 128, n0 = blockIdx.x * 128;
    const uint32_t sbase = smem_u32(sm);

    const int warp_m = wid & 1;
    const int warp_n = wid >> 1;
    const int a_row = warp_m * 64 + (lane & 15);
    const int a_k8  = lane >> 4;
    const int b_row = warp_n * 64 + (lane & 7) + ((lane >> 4) << 3);
    const int b_k8  = (lane >> 3) & 1;

    float acc[4][8][4];
#pragma unroll
    for (int a = 0; a < 4; a++)
#pragma unroll
        for (int b = 0; b < 8; b++)
#pragma unroll
            for (int cq = 0; cq < 4; cq++) acc[a][b][cq] = 0.0f;

    GEMM_MAINLOOP(Ah + (size_t)m0 * K, Bh + (size_t)n0 * K, K);

    const int crow = m0 + warp_m * 64 + (lane >> 2);
    const int ccol = n0 + warp_n * 64 + (lane & 3) * 2;
#pragma unroll
    for (int j = 0; j < 8; j++) {
        int col = ccol + j * 8;
        float b0 = bias[col], b1 = bias[col + 1];
#pragma unroll
        for (int mt = 0; mt < 4; mt++) {
            int r0 = crow + mt * 16;
            float2 o0 = make_float2(acc[mt][j][0] + b0, acc[mt][j][1] + b1);
            float2 o1 = make_float2(acc[mt][j][2] + b0, acc[mt][j][3] + b1);
            *(float2*)(Cm + (size_t)r0 * N + col)       = o0;
            *(float2*)(Cm + (size_t)(r0 + 8) * N + col) = o1;
        }
    }
}

// ============================================================
// HMMA sliding-window attention (R12 version; arithmetic lo/hi)
// ============================================================
__global__ __launch_bounds__(256) void attn_mma_kernel(
    const __half* __restrict__ qh, const __half* __restrict__ kh,
    const __half* __restrict__ vh, __half* __restrict__ att)
{
    __shared__ __half Qs[2][64 * 64];
    __shared__ __half Ks[2][64 * 64];
    __shared__ __half Vs[2][64 * 64];

    const int t = threadIdx.x, wid = t >> 5, lane = t & 31;
    const int wm = wid & 3, hsel = wid >> 2;
    const int q0 = blockIdx.x * 64;
    const int hp = blockIdx.y;
    const int b  = blockIdx.z;
    const int h  = hp * 2 + hsel;
    const int hk = hp >> 1;

    const __half* Kg = kh + ((size_t)(b * HKVn + hk) * Sn) * 64;
    const __half* Vg = vh + ((size_t)(b * HKVn + hk) * Sn) * 64;

    const uint32_t sQ = smem_u32(Qs[hsel]);
    const uint32_t sK = smem_u32(Ks);
    const uint32_t sV = smem_u32(Vs);

    {
        const uint32_t sQ0 = smem_u32(Qs);
        for (int i = t; i < 1024; i += 256) {
            int hs = i >> 9, row = (i >> 3) & 63, c = i & 7;
            uint32_t sw = (uint32_t)hs * 8192u + (uint32_t)row * 128u +
                          (uint32_t)((c ^ (row & 7)) << 4);
            cp16(sQ0 + sw,
                 qh + (((size_t)(b * Hn + hp * 2 + hs) * Sn) + q0 + row) * 64 + c * 8);
        }
    }

    // tile it covers keys [q0-128+64*it, q0-64+64*it); valid tiles:
    const int lo = (q0 >= 128) ? 0 : (2 - (q0 >> 6));
    const int hi = (q0 + 192 + 64 <= Sn) ? 4 : (2 + ((Sn - 64 - q0) >> 6));

#define PREFETCH(it, buf) do { \
    int kb_ = q0 - 128 + (it) * 64; \
    const __half* Kt_ = Kg + (size_t)kb_ * 64; \
    const __half* Vt_ = Vg + (size_t)kb_ * 64; \
    uint32_t sk_ = sK + (uint32_t)(buf) * 8192u; \
    uint32_t sv_ = sV + (uint32_t)(buf) * 8192u; \
    for (int i_ = t; i_ < 512; i_ += 256) { \
        int row_ = i_ >> 3, c_ = i_ & 7; \
        uint32_t sw_ = (uint32_t)row_ * 128u + (uint32_t)((c_ ^ (row_ & 7)) << 4); \
        cp16(sk_ + sw_, Kt_ + row_ * 64 + c_ * 8); \
        cp16(sv_ + sw_, Vt_ + row_ * 64 + c_ * 8); \
    } } while (0)

    PREFETCH(lo, 0);
    CP_COMMIT();

    const int arow = wm * 16 + (lane & 15);
    const int ak8  = lane >> 4;
    const int brow = (lane & 7) + ((lane >> 4) << 3);
    const int bk8  = (lane >> 3) & 1;
    const int vrow = (lane & 7) + (((lane >> 3) & 1) << 3);
    const int vc8  = lane >> 4;

    const int r0g = q0 + wm * 16 + (lane >> 2);
    const int r1g = r0g + 8;

    float acc[8][4];
#pragma unroll
    for (int g = 0; g < 8; g++)
#pragma unroll
        for (int e = 0; e < 4; e++) acc[g][e] = 0.0f;
    float l0 = 0.0f, l1 = 0.0f;

    uint32_t qf[4][4];
    bool qloaded = false;

    for (int it = lo; it <= hi; ++it) {
        const int buf = (it - lo) & 1;
        if (it < hi) { PREFETCH(it + 1, buf ^ 1); CP_COMMIT(); CP_WAIT1(); }
        else { CP_WAIT0(); }
        __syncthreads();

        if (!qloaded) {
#pragma unroll
            for (int kblk = 0; kblk < 4; kblk++) {
                uint32_t ad = sQ + (uint32_t)arow * 128u +
                              (uint32_t)(((kblk * 2 + ak8) ^ (arow & 7)) << 4);
                ldmx4(qf[kblk], ad);
            }
            qloaded = true;
        }

        const int kb = q0 - 128 + it * 64;
        const uint32_t sk = sK + (uint32_t)buf * 8192u;
        const uint32_t sv = sV + (uint32_t)buf * 8192u;
        const bool need_mask = (it == 0) || (it == 4);

        float sc[8][4];
#pragma unroll
        for (int g = 0; g < 8; g++)
#pragma unroll
            for (int e = 0; e < 4; e++) sc[g][e] = 0.0f;
#pragma unroll
        for (int kblk = 0; kblk < 4; kblk++) {
#pragma unroll
            for (int g = 0; g < 4; g++) {
                int r = g * 16 + brow;
                uint32_t bd = sk + (uint32_t)r * 128u +
                              (uint32_t)(((kblk * 2 + bk8) ^ (r & 7)) << 4);
                uint32_t bf[4];
                ldmx4(bf, bd);
                mma16816(sc[2 * g],     qf[kblk], bf);
                mma16816(sc[2 * g + 1], qf[kblk], bf + 2);
            }
        }

        uint32_t pf[8][2];
        if (need_mask) {
#pragma unroll
            for (int g = 0; g < 8; g++) {
                int j0 = kb + g * 8 + (lane & 3) * 2;
                int j1 = j0 + 1;
                float p0 = (abs(j0 - r0g) <= 128) ? ex2f(sc[g][0]) : 0.0f;
                float p1 = (abs(j1 - r0g) <= 128) ? ex2f(sc[g][1]) : 0.0f;
                float p2 = (abs(j0 - r1g) <= 128) ? ex2f(sc[g][2]) : 0.0f;
                float p3 = (abs(j1 - r1g) <= 128) ? ex2f(sc[g][3]) : 0.0f;
                l0 += p0 + p1;
                l1 += p2 + p3;
                pf[g][0] = pack_h2(p0, p1);
                pf[g][1] = pack_h2(p2, p3);
            }
        } else {
#pragma unroll
            for (int g = 0; g < 8; g++) {
                float p0 = ex2f(sc[g][0]);
                float p1 = ex2f(sc[g][1]);
                float p2 = ex2f(sc[g][2]);
                float p3 = ex2f(sc[g][3]);
                l0 += p0 + p1;
                l1 += p2 + p3;
                pf[g][0] = pack_h2(p0, p1);
                pf[g][1] = pack_h2(p2, p3);
            }
        }

#pragma unroll
        for (int jj = 0; jj < 4; jj++) {
            uint32_t a[4] = { pf[2 * jj][0], pf[2 * jj][1],
                              pf[2 * jj + 1][0], pf[2 * jj + 1][1] };
#pragma unroll
            for (int dg = 0; dg < 4; dg++) {
                int r = jj * 16 + vrow;
                uint32_t bd = sv + (uint32_t)r * 128u +
                              (uint32_t)(((dg * 2 + vc8) ^ (r & 7)) << 4);
                uint32_t bf[4];
                ldmx4t(bf, bd);
                mma16816(acc[2 * dg],     a, bf);
                mma16816(acc[2 * dg + 1], a, bf + 2);
            }
        }
        __syncthreads();
    }
#undef PREFETCH

    l0 += __shfl_xor_sync(0xffffffffu, l0, 1);
    l0 += __shfl_xor_sync(0xffffffffu, l0, 2);
    l1 += __shfl_xor_sync(0xffffffffu, l1, 1);
    l1 += __shfl_xor_sync(0xffffffffu, l1, 2);
    const float i0 = 1.0f / l0, i1 = 1.0f / l1;
    const size_t base0 = ((size_t)(b * Sn) + r0g) * (Hn * DHn) + h * 64;
    const size_t base1 = ((size_t)(b * Sn) + r1g) * (Hn * DHn) + h * 64;
#pragma unroll
    for (int g = 0; g < 8; g++) {
        int d = g * 8 + (lane & 3) * 2;
        *(uint32_t*)(att + base0 + d) = pack_h2(acc[g][0] * i0, acc[g][1] * i0);
        *(uint32_t*)(att + base1 + d) = pack_h2(acc[g][2] * i1, acc[g][3] * i1);
    }
}

// ============================================================
extern "C" void kernel_launch(void* const* d_in, const int* in_sizes, int n_in,
                              void* d_out, int out_size)
{
    const float* x    = (const float*)d_in[0];
    const float* Wq   = (const float*)d_in[1];
    const float* bq   = (const float*)d_in[2];
    const float* Wk   = (const float*)d_in[3];
    const float* bk   = (const float*)d_in[4];
    const float* Wv   = (const float*)d_in[5];
    const float* bv   = (const float*)d_in[6];
    const float* Wo   = (const float*)d_in[7];
    const float* bo   = (const float*)d_in[8];
    const float* qn   = (const float*)d_in[9];
    const float* kn   = (const float*)d_in[10];
    const float* cosT = (const float*)d_in[11];
    const float* sinT = (const float*)d_in[12];
    float* out = (float*)d_out;

    __half *xh, *qh, *kh, *vh, *ah, *wqkv, *wo;
    cudaGetSymbolAddress((void**)&xh,   g_xh);
    cudaGetSymbolAddress((void**)&qh,   g_qh);
    cudaGetSymbolAddress((void**)&kh,   g_kh);
    cudaGetSymbolAddress((void**)&vh,   g_vh);
    cudaGetSymbolAddress((void**)&ah,   g_ah);
    cudaGetSymbolAddress((void**)&wqkv, g_wqkv);
    cudaGetSymbolAddress((void**)&wo,   g_wo);

    cudaFuncSetAttribute(mm_qkv_fused_kernel,
                         cudaFuncAttributeMaxDynamicSharedMemorySize, 65536);
    cudaFuncSetAttribute(mm_hmma_kernel,
                         cudaFuncAttributeMaxDynamicSharedMemorySize, 65536);
    const int DSMEM = 65536;

    prep_kernel<<<2560 + 4096, 256>>>(x, Wq, Wk, Wv, Wo, xh, wqkv, wo);

    mm_qkv_fused_kernel<<<dim3(12, 128), 128, DSMEM>>>(
        xh, wqkv, bq, bk, bv, qn, kn, cosT, sinT, qh, kh, vh);

    attn_mma_kernel<<<dim3(Sn / 64, Hn / 2, Bn), 256>>>(qh, kh, vh, ah);

    mm_hmma_kernel<<<dim3(8, 128), 128, DSMEM>>>(ah, wo, bo, out, 1024, 1024);
}